// round 9
// baseline (speedup 1.0000x reference)
#include <cuda_runtime.h>
#include <mma.h>
#include <math.h>
#include <stdint.h>
#include <cuda_fp16.h>

using namespace nvcuda;

#define BB 2
#define SS 2048
#define EE 2048
#define HH 16
#define DD 128
#define N3 6144            // 3*EE
#define MM (BB*SS)         // 4096
#define KK EE              // 2048

#define LDAH 40            // GEMM A smem row stride (halves)
#define LDBH 136           // GEMM B smem row stride (halves)
#define LDC  132           // GEMM epilogue staging stride (floats)

// Scratch (static device globals — allowed; no runtime allocation)
__device__ __half g_xh [(size_t)MM * KK];           // X in fp16 (RN)
__device__ __half g_wh [(size_t)KK * N3];           // W in fp16 (RN)
__device__ float2 g_sc [(size_t)SS * DD];           // sin/cos table for t = s*128+d
__device__ __half g_qh [(size_t)BB * HH * SS * DD]; // Q roped+scaled, [b][h][s][d]
__device__ __half g_kh [(size_t)BB * HH * SS * DD]; // K roped,        [b][h][s][d]
__device__ __half g_vt [(size_t)BB * HH * DD * SS]; // V transposed,   [b][h][d][s]

// ---------------------------------------------------------------------------
// Helpers
// ---------------------------------------------------------------------------
__device__ __forceinline__ void cp_async16(void* dst_smem, const void* src_gmem) {
    unsigned int dst = (unsigned int)__cvta_generic_to_shared(dst_smem);
    asm volatile("cp.async.cg.shared.global [%0], [%1], 16;\n" :: "r"(dst), "l"(src_gmem));
}
__device__ __forceinline__ void cp_commit() {
    asm volatile("cp.async.commit_group;\n" ::: "memory");
}
template <int N>
__device__ __forceinline__ void cp_wait() {
    asm volatile("cp.async.wait_group %0;\n" :: "n"(N) : "memory");
}
// mma.sync m16n8k16 fp16 -> fp32, documented lane mapping
__device__ __forceinline__ void mma_f16(float* c, const unsigned* a, const unsigned* b) {
    asm volatile(
        "mma.sync.aligned.m16n8k16.row.col.f32.f16.f16.f32 "
        "{%0,%1,%2,%3}, {%4,%5,%6,%7}, {%8,%9}, {%0,%1,%2,%3};"
        : "+f"(c[0]), "+f"(c[1]), "+f"(c[2]), "+f"(c[3])
        : "r"(a[0]), "r"(a[1]), "r"(a[2]), "r"(a[3]), "r"(b[0]), "r"(b[1]));
}

// ---------------------------------------------------------------------------
// Prep kernels
// ---------------------------------------------------------------------------
__global__ __launch_bounds__(256) void cvt_x(const float* __restrict__ X) {
    size_t i = ((size_t)blockIdx.x * 256 + threadIdx.x) * 8;
    float4 v0 = *(const float4*)(X + i);
    float4 v1 = *(const float4*)(X + i + 4);
    __half2 h[4] = { __floats2half2_rn(v0.x, v0.y), __floats2half2_rn(v0.z, v0.w),
                     __floats2half2_rn(v1.x, v1.y), __floats2half2_rn(v1.z, v1.w) };
    *(uint4*)(g_xh + i) = *(uint4*)h;
}
__global__ __launch_bounds__(256) void cvt_w(const float* __restrict__ W) {
    size_t i = ((size_t)blockIdx.x * 256 + threadIdx.x) * 8;
    float4 v0 = *(const float4*)(W + i);
    float4 v1 = *(const float4*)(W + i + 4);
    __half2 h[4] = { __floats2half2_rn(v0.x, v0.y), __floats2half2_rn(v0.z, v0.w),
                     __floats2half2_rn(v1.x, v1.y), __floats2half2_rn(v1.z, v1.w) };
    *(uint4*)(g_wh + i) = *(uint4*)h;
}
// sin/cos table: g_sc[i] = {sin(i), cos(i)} for i = s*128+d
__global__ __launch_bounds__(256) void sc_table() {
    int i = blockIdx.x * 256 + threadIdx.x;
    float sv, cv;
    sincosf((float)i, &sv, &cv);
    g_sc[i] = make_float2(sv, cv);
}

// ---------------------------------------------------------------------------
// Kernel 1: QKV GEMM (fp16 wmma 16x16x16, fp32 accum), fused epilogue.
// 128x128 tile, BK=32, 256 threads (8 warps: wm=wid&1 -> 64 m-rows,
// wn=wid>>1 -> 32 n-cols; acc 4x2 frags). 3-stage cp.async ring with ONE
// __syncthreads per iteration. Epilogue staged in two 64-row halves.
// smem: 3 stages * 18944 B = 56832 B (half-Cs 33792 B reuses it).
// __launch_bounds__(256,2) -> 2 CTAs/SM.
// ---------------------------------------------------------------------------
#define STAGE_H (128 * LDAH + 32 * LDBH)   // halves per stage: 9472
#define GEMM_SMEM (3 * STAGE_H * 2)        // 56832 B

__device__ __forceinline__ void load_tiles(__half* As, __half* Bs,
                                           int m0, int n0, int kt, int tid) {
    #pragma unroll
    for (int i = 0; i < 2; i++) {      // A: 128 rows x 32 halves = 512 chunks
        int idx = tid + i * 256;
        int row = idx >> 2;
        int c8 = (idx & 3) << 3;
        cp_async16(As + row * LDAH + c8, g_xh + (size_t)(m0 + row) * KK + kt + c8);
    }
    #pragma unroll
    for (int i = 0; i < 2; i++) {      // B: 32 rows x 128 halves = 512 chunks
        int idx = tid + i * 256;
        int row = idx >> 4;
        int c8 = (idx & 15) << 3;
        cp_async16(Bs + row * LDBH + c8, g_wh + (size_t)(kt + row) * N3 + n0 + c8);
    }
}

__global__ __launch_bounds__(256, 2) void qkv_gemm(const float* __restrict__ bias) {
    extern __shared__ char smraw[];
    __half* stg[3] = { (__half*)smraw, (__half*)smraw + STAGE_H,
                       (__half*)smraw + 2 * STAGE_H };

    const int tid = threadIdx.x;
    const int wid = tid >> 5;
    const int wm = wid & 1;            // 0..1 -> m offset wm*64
    const int wn = wid >> 1;           // 0..3 -> n offset wn*32
    const int m0 = blockIdx.y * 128;
    const int n0 = blockIdx.x * 128;

    wmma::fragment<wmma::accumulator, 16, 16, 16, float> acc[4][2];
    #pragma unroll
    for (int i = 0; i < 4; i++)
        #pragma unroll
        for (int j = 0; j < 2; j++) wmma::fill_fragment(acc[i][j], 0.0f);

    load_tiles(stg[0], stg[0] + 128 * LDAH, m0, n0, 0, tid);
    cp_commit();
    load_tiles(stg[1], stg[1] + 128 * LDAH, m0, n0, 32, tid);
    cp_commit();

    const int NT = KK / 32;            // 64
    for (int t = 0; t < NT; t++) {
        const int s = t % 3;
        if (t == NT - 1) cp_wait<0>(); else cp_wait<1>();
        __syncthreads();

        if (t + 2 < NT) {
            const int sn = (t + 2) % 3;
            load_tiles(stg[sn], stg[sn] + 128 * LDAH, m0, n0, (t + 2) * 32, tid);
        }
        cp_commit();                   // one group per iteration (may be empty)

        const __half* Asb = stg[s];
        const __half* Bsb = stg[s] + 128 * LDAH;
        #pragma unroll
        for (int kk = 0; kk < 32; kk += 16) {
            wmma::fragment<wmma::matrix_a, 16, 16, 16, __half, wmma::row_major> a[4];
            wmma::fragment<wmma::matrix_b, 16, 16, 16, __half, wmma::row_major> b[2];
            #pragma unroll
            for (int i = 0; i < 4; i++)
                wmma::load_matrix_sync(a[i], Asb + (wm * 64 + i * 16) * LDAH + kk, LDAH);
            #pragma unroll
            for (int j = 0; j < 2; j++)
                wmma::load_matrix_sync(b[j], Bsb + kk * LDBH + wn * 32 + j * 16, LDBH);
            #pragma unroll
            for (int i = 0; i < 4; i++)
                #pragma unroll
                for (int j = 0; j < 2; j++)
                    wmma::mma_sync(acc[i][j], a[i], b[j], acc[i][j]);
        }
    }
    __syncthreads();

    // ---- Fused epilogue in two 64-row halves (Cs reuses stage smem) ----
    float* Cs = (float*)smraw;         // 64 x 132 fp32 = 33792 B
    const int which = n0 >> 11;        // 0=q, 1=k, 2=v
    const int h = (n0 & 2047) >> 7;
    const int b = m0 >> 11;
    const int s_base = m0 & 2047;

    #pragma unroll
    for (int half = 0; half < 2; half++) {
        if (wm == half) {
            #pragma unroll
            for (int i = 0; i < 4; i++)
                #pragma unroll
                for (int j = 0; j < 2; j++)
                    wmma::store_matrix_sync(Cs + (size_t)(i * 16) * LDC + wn * 32 + j * 16,
                                            acc[i][j], LDC, wmma::mem_row_major);
        }
        __syncthreads();

        if (which < 2) {
            __half* dstb = (which == 0 ? g_qh : g_kh) + ((size_t)(b * HH + h) * SS) * DD;
            const float scale = (which == 0) ? 0.08838834764831845f : 1.0f;
            #pragma unroll
            for (int i = 0; i < 8; i++) {
                int idx = tid + i * 256;        // 2048 float4 slots
                int row = idx >> 5;             // 0..63
                int c4 = (idx & 31) << 2;
                int s = s_base + half * 64 + row;
                float4 u = *(const float4*)(Cs + row * LDC + c4);
                float4 w = *(const float4*)(Cs + row * LDC + (c4 ^ 64));
                float4 bu = *(const float4*)(bias + n0 + c4);
                float4 bw = *(const float4*)(bias + n0 + (c4 ^ 64));
                u.x += bu.x; u.y += bu.y; u.z += bu.z; u.w += bu.w;
                w.x += bw.x; w.y += bw.y; w.z += bw.z; w.w += bw.w;
                float sgn = (c4 < 64) ? -1.0f : 1.0f;
                const float2* scp = g_sc + (size_t)s * DD + c4;
                float2 sc0 = scp[0], sc1 = scp[1], sc2 = scp[2], sc3 = scp[3];
                float r0 = (u.x * sc0.y + sgn * w.x * sc0.x) * scale;
                float r1 = (u.y * sc1.y + sgn * w.y * sc1.x) * scale;
                float r2 = (u.z * sc2.y + sgn * w.z * sc2.x) * scale;
                float r3 = (u.w * sc3.y + sgn * w.w * sc3.x) * scale;
                __half* dp = dstb + (size_t)s * DD + c4;
                *(__half2*)(dp) = __floats2half2_rn(r0, r1);
                *(__half2*)(dp + 2) = __floats2half2_rn(r2, r3);
            }
        } else {
            __half* dstb = g_vt + ((size_t)(b * HH + h) * DD) * SS + s_base + half * 64;
            #pragma unroll
            for (int i = 0; i < 8; i++) {
                int idx = tid + i * 256;
                int d = idx >> 4;               // 0..127
                int s4 = (idx & 15) << 2;       // 0..60
                float bv = bias[n0 + d];
                float v0 = Cs[(s4 + 0) * LDC + d] + bv;
                float v1 = Cs[(s4 + 1) * LDC + d] + bv;
                float v2 = Cs[(s4 + 2) * LDC + d] + bv;
                float v3 = Cs[(s4 + 3) * LDC + d] + bv;
                __half* dp = dstb + (size_t)d * SS + s4;
                *(__half2*)(dp) = __floats2half2_rn(v0, v1);
                *(__half2*)(dp + 2) = __floats2half2_rn(v2, v3);
            }
        }
        __syncthreads();
    }
}

// ---------------------------------------------------------------------------
// Kernel 3: flash attention via fp16 mma.sync (m16n8k16, fp32 accum).
// 512 threads (16 warps). BM=BN=128, D=128. P overwrites K smem. (Unchanged.)
// ---------------------------------------------------------------------------
#define LDQH2 136
#define ATT_SMEM (3 * 128 * LDQH2 * 2 + 1024 * 4)

__global__ __launch_bounds__(512, 1) void attn_tc(float* __restrict__ out) {
    extern __shared__ char smraw[];
    __half* Qs = (__half*)smraw;             // [128][136]
    __half* KP = Qs + 128 * LDQH2;           // K tile, later P tile
    __half* Vt = KP + 128 * LDQH2;           // V^T tile: [d][s]
    float* mpart = (float*)(Vt + 128 * LDQH2);
    float* lpart = mpart + 512;

    const int tid = threadIdx.x;
    const int wid = tid >> 5;
    const int lane = tid & 31;
    const int wm = wid & 3;
    const int wn = wid >> 2;
    const int g = lane >> 2;
    const int q = lane & 3;
    const int rbase = wm * 32;
    const int s0 = blockIdx.x * 128;
    const int h = blockIdx.y;
    const int b = blockIdx.z;

    const __half* qg = g_qh + ((size_t)(b * HH + h) * SS + s0) * DD;
    const __half* kg = g_kh + ((size_t)(b * HH + h) * SS) * DD;
    const __half* vtg = g_vt + ((size_t)(b * HH + h) * DD) * SS;

    #pragma unroll
    for (int i = 0; i < 4; i++) {
        int idx = tid + i * 512;
        int row = idx >> 4;
        int c8 = (idx & 15) << 3;
        cp_async16(Qs + row * LDQH2 + c8, qg + (size_t)row * DD + c8);
    }
    cp_commit();
    #pragma unroll
    for (int i = 0; i < 4; i++) {
        int idx = tid + i * 512;
        int row = idx >> 4;
        int c8 = (idx & 15) << 3;
        cp_async16(KP + row * LDQH2 + c8, kg + (size_t)row * DD + c8);
    }
    cp_commit();
    #pragma unroll
    for (int i = 0; i < 4; i++) {
        int idx = tid + i * 512;
        int row = idx >> 4;
        int c8 = (idx & 15) << 3;
        cp_async16(Vt + row * LDQH2 + c8, vtg + (size_t)row * SS + c8);
    }
    cp_commit();

    float o[2][4][4];
    #pragma unroll
    for (int mf = 0; mf < 2; mf++)
        #pragma unroll
        for (int nf = 0; nf < 4; nf++)
            #pragma unroll
            for (int e = 0; e < 4; e++) o[mf][nf][e] = 0.0f;
    float m_run[2][2] = {{-1e30f, -1e30f}, {-1e30f, -1e30f}};
    float l_run[2][2] = {{0.0f, 0.0f}, {0.0f, 0.0f}};

    for (int t = 0; t < SS / 128; t++) {
        cp_wait<1>();
        __syncthreads();

        float s_[2][4][4];
        #pragma unroll
        for (int mf = 0; mf < 2; mf++)
            #pragma unroll
            for (int nf = 0; nf < 4; nf++)
                #pragma unroll
                for (int e = 0; e < 4; e++) s_[mf][nf][e] = 0.0f;

        #pragma unroll
        for (int kk = 0; kk < 8; kk++) {
            unsigned a[2][4];
            #pragma unroll
            for (int mf = 0; mf < 2; mf++) {
                const __half* qp = Qs + (rbase + mf * 16 + g) * LDQH2 + kk * 16 + q * 2;
                a[mf][0] = *(const unsigned*)(qp);
                a[mf][1] = *(const unsigned*)(qp + 8 * LDQH2);
                a[mf][2] = *(const unsigned*)(qp + 8);
                a[mf][3] = *(const unsigned*)(qp + 8 * LDQH2 + 8);
            }
            #pragma unroll
            for (int nf = 0; nf < 4; nf++) {
                const __half* kp = KP + (wn * 32 + nf * 8 + g) * LDQH2 + kk * 16 + q * 2;
                unsigned bf[2] = { *(const unsigned*)(kp), *(const unsigned*)(kp + 8) };
                mma_f16(s_[0][nf], a[0], bf);
                mma_f16(s_[1][nf], a[1], bf);
            }
        }

        float lm[2][2] = {{-1e30f, -1e30f}, {-1e30f, -1e30f}};
        #pragma unroll
        for (int mf = 0; mf < 2; mf++)
            #pragma unroll
            for (int nf = 0; nf < 4; nf++) {
                lm[mf][0] = fmaxf(lm[mf][0], fmaxf(s_[mf][nf][0], s_[mf][nf][1]));
                lm[mf][1] = fmaxf(lm[mf][1], fmaxf(s_[mf][nf][2], s_[mf][nf][3]));
            }
        #pragma unroll
        for (int off = 1; off <= 2; off <<= 1)
            #pragma unroll
            for (int mf = 0; mf < 2; mf++)
                #pragma unroll
                for (int hf = 0; hf < 2; hf++)
                    lm[mf][hf] = fmaxf(lm[mf][hf],
                                       __shfl_xor_sync(0xffffffffu, lm[mf][hf], off));
        if (q == 0) {
            #pragma unroll
            for (int mf = 0; mf < 2; mf++)
                #pragma unroll
                for (int hf = 0; hf < 2; hf++)
                    mpart[wn * 128 + rbase + mf * 16 + g + hf * 8] = lm[mf][hf];
        }
        __syncthreads();

        float mnew[2][2], al[2][2];
        #pragma unroll
        for (int mf = 0; mf < 2; mf++)
            #pragma unroll
            for (int hf = 0; hf < 2; hf++) {
                int r = rbase + mf * 16 + g + hf * 8;
                float mv = fmaxf(fmaxf(mpart[r], mpart[128 + r]),
                                 fmaxf(mpart[256 + r], mpart[384 + r]));
                float mn = fmaxf(m_run[mf][hf], mv);
                al[mf][hf] = __expf(m_run[mf][hf] - mn);
                m_run[mf][hf] = mn;
                mnew[mf][hf] = mn;
            }
        float ls[2][2] = {{0.0f, 0.0f}, {0.0f, 0.0f}};
        #pragma unroll
        for (int mf = 0; mf < 2; mf++)
            #pragma unroll
            for (int nf = 0; nf < 4; nf++) {
                float p0 = __expf(s_[mf][nf][0] - mnew[mf][0]);
                float p1 = __expf(s_[mf][nf][1] - mnew[mf][0]);
                float p2 = __expf(s_[mf][nf][2] - mnew[mf][1]);
                float p3 = __expf(s_[mf][nf][3] - mnew[mf][1]);
                ls[mf][0] += p0 + p1;
                ls[mf][1] += p2 + p3;
                int col = wn * 32 + nf * 8 + q * 2;
                *(__half2*)(KP + (rbase + mf * 16 + g) * LDQH2 + col) =
                    __floats2half2_rn(p0, p1);
                *(__half2*)(KP + (rbase + mf * 16 + g + 8) * LDQH2 + col) =
                    __floats2half2_rn(p2, p3);
            }
        #pragma unroll
        for (int off = 1; off <= 2; off <<= 1)
            #pragma unroll
            for (int mf = 0; mf < 2; mf++)
                #pragma unroll
                for (int hf = 0; hf < 2; hf++)
                    ls[mf][hf] += __shfl_xor_sync(0xffffffffu, ls[mf][hf], off);
        if (q == 0) {
            #pragma unroll
            for (int mf = 0; mf < 2; mf++)
                #pragma unroll
                for (int hf = 0; hf < 2; hf++)
                    lpart[wn * 128 + rbase + mf * 16 + g + hf * 8] = ls[mf][hf];
        }
        cp_wait<0>();
        __syncthreads();

        #pragma unroll
        for (int mf = 0; mf < 2; mf++)
            #pragma unroll
            for (int hf = 0; hf < 2; hf++) {
                int r = rbase + mf * 16 + g + hf * 8;
                float lsum = lpart[r] + lpart[128 + r] + lpart[256 + r] + lpart[384 + r];
                l_run[mf][hf] = l_run[mf][hf] * al[mf][hf] + lsum;
            }
        #pragma unroll
        for (int mf = 0; mf < 2; mf++)
            #pragma unroll
            for (int nf = 0; nf < 4; nf++) {
                o[mf][nf][0] *= al[mf][0];
                o[mf][nf][1] *= al[mf][0];
                o[mf][nf][2] *= al[mf][1];
                o[mf][nf][3] *= al[mf][1];
            }

        #pragma unroll
        for (int kk = 0; kk < 8; kk++) {
            unsigned a[2][4];
            #pragma unroll
            for (int mf = 0; mf < 2; mf++) {
                const __half* pp = KP + (rbase + mf * 16 + g) * LDQH2 + kk * 16 + q * 2;
                a[mf][0] = *(const unsigned*)(pp);
                a[mf][1] = *(const unsigned*)(pp + 8 * LDQH2);
                a[mf][2] = *(const unsigned*)(pp + 8);
                a[mf][3] = *(const unsigned*)(pp + 8 * LDQH2 + 8);
            }
            #pragma unroll
            for (int nf = 0; nf < 4; nf++) {
                const __half* vp = Vt + (wn * 32 + nf * 8 + g) * LDQH2 + kk * 16 + q * 2;
                unsigned bf[2] = { *(const unsigned*)(vp), *(const unsigned*)(vp + 8) };
                mma_f16(o[0][nf], a[0], bf);
                mma_f16(o[1][nf], a[1], bf);
            }
        }
        __syncthreads();

        if (t + 1 < SS / 128) {
            const __half* kn = kg + (size_t)(t + 1) * 128 * DD;
            const __half* vn = vtg + (size_t)(t + 1) * 128;
            #pragma unroll
            for (int i = 0; i < 4; i++) {
                int idx = tid + i * 512;
                int row = idx >> 4;
                int c8 = (idx & 15) << 3;
                cp_async16(KP + row * LDQH2 + c8, kn + (size_t)row * DD + c8);
            }
            cp_commit();
            #pragma unroll
            for (int i = 0; i < 4; i++) {
                int idx = tid + i * 512;
                int row = idx >> 4;
                int c8 = (idx & 15) << 3;
                cp_async16(Vt + row * LDQH2 + c8, vn + (size_t)row * SS + c8);
            }
            cp_commit();
        }
    }

    float inv[2][2];
    #pragma unroll
    for (int mf = 0; mf < 2; mf++)
        #pragma unroll
        for (int hf = 0; hf < 2; hf++)
            inv[mf][hf] = 1.0f / l_run[mf][hf];

    #pragma unroll
    for (int mf = 0; mf < 2; mf++)
        #pragma unroll
        for (int nf = 0; nf < 4; nf++) {
            int col = wn * 32 + nf * 8 + q * 2;
            int row0 = s0 + rbase + mf * 16 + g;
            float2 w0 = { o[mf][nf][0] * inv[mf][0], o[mf][nf][1] * inv[mf][0] };
            float2 w1 = { o[mf][nf][2] * inv[mf][1], o[mf][nf][3] * inv[mf][1] };
            *(float2*)(out + ((size_t)(b * SS + row0) * HH + h) * DD + col) = w0;
            *(float2*)(out + ((size_t)(b * SS + row0 + 8) * HH + h) * DD + col) = w1;
        }
}

// ---------------------------------------------------------------------------
extern "C" void kernel_launch(void* const* d_in, const int* in_sizes, int n_in,
                              void* d_out, int out_size) {
    const float* x    = (const float*)d_in[0];
    const float* W    = (const float*)d_in[1];
    const float* bias = (const float*)d_in[2];
    float* out = (float*)d_out;

    cvt_x<<<(int)((size_t)MM * KK / 2048), 256>>>(x);
    cvt_w<<<(int)((size_t)KK * N3 / 2048), 256>>>(W);
    sc_table<<<SS * DD / 256, 256>>>();

    cudaFuncSetAttribute(qkv_gemm, cudaFuncAttributeMaxDynamicSharedMemorySize, GEMM_SMEM);
    dim3 g1(N3 / 128, MM / 128);
    qkv_gemm<<<g1, 256, GEMM_SMEM>>>(bias);

    cudaFuncSetAttribute(attn_tc, cudaFuncAttributeMaxDynamicSharedMemorySize, ATT_SMEM);
    dim3 g3(SS / 128, HH, BB);
    attn_tc<<<g3, 512, ATT_SMEM>>>(out);
}

// round 10
// speedup vs baseline: 1.1029x; 1.1029x over previous
#include <cuda_runtime.h>
#include <mma.h>
#include <math.h>
#include <stdint.h>
#include <cuda_fp16.h>

#define BB 2
#define SS 2048
#define EE 2048
#define HH 16
#define DD 128
#define N3 6144            // 3*EE
#define MM (BB*SS)         // 4096
#define KK EE              // 2048

#define LDA2 40            // smem row stride (halves) for A and B(nk) tiles
#define LDC  132           // epilogue staging stride (floats)

// Scratch (static device globals — allowed; no runtime allocation)
__device__ __half g_xh [(size_t)MM * KK];           // X in fp16 (RN)
__device__ __half g_wt [(size_t)N3 * KK];           // W^T in fp16 (RN), [n][k]
__device__ float2 g_sc [(size_t)SS * DD];           // sin/cos table for t = s*128+d
__device__ __half g_qh [(size_t)BB * HH * SS * DD]; // Q roped+scaled, [b][h][s][d]
__device__ __half g_kh [(size_t)BB * HH * SS * DD]; // K roped,        [b][h][s][d]
__device__ __half g_vt [(size_t)BB * HH * DD * SS]; // V transposed,   [b][h][d][s]

// ---------------------------------------------------------------------------
// Helpers
// ---------------------------------------------------------------------------
__device__ __forceinline__ void cp_async16(void* dst_smem, const void* src_gmem) {
    unsigned int dst = (unsigned int)__cvta_generic_to_shared(dst_smem);
    asm volatile("cp.async.cg.shared.global [%0], [%1], 16;\n" :: "r"(dst), "l"(src_gmem));
}
__device__ __forceinline__ void cp_commit() {
    asm volatile("cp.async.commit_group;\n" ::: "memory");
}
template <int N>
__device__ __forceinline__ void cp_wait() {
    asm volatile("cp.async.wait_group %0;\n" :: "n"(N) : "memory");
}
// mma.sync m16n8k16 fp16 -> fp32, documented lane mapping
__device__ __forceinline__ void mma_f16(float* c, const unsigned* a, const unsigned* b) {
    asm volatile(
        "mma.sync.aligned.m16n8k16.row.col.f32.f16.f16.f32 "
        "{%0,%1,%2,%3}, {%4,%5,%6,%7}, {%8,%9}, {%0,%1,%2,%3};"
        : "+f"(c[0]), "+f"(c[1]), "+f"(c[2]), "+f"(c[3])
        : "r"(a[0]), "r"(a[1]), "r"(a[2]), "r"(a[3]), "r"(b[0]), "r"(b[1]));
}

// ---------------------------------------------------------------------------
// Prep kernels
// ---------------------------------------------------------------------------
__global__ __launch_bounds__(256) void cvt_x(const float* __restrict__ X) {
    size_t i = ((size_t)blockIdx.x * 256 + threadIdx.x) * 8;
    float4 v0 = *(const float4*)(X + i);
    float4 v1 = *(const float4*)(X + i + 4);
    __half2 h[4] = { __floats2half2_rn(v0.x, v0.y), __floats2half2_rn(v0.z, v0.w),
                     __floats2half2_rn(v1.x, v1.y), __floats2half2_rn(v1.z, v1.w) };
    *(uint4*)(g_xh + i) = *(uint4*)h;
}
// Transpose W [k][n] fp32 -> g_wt [n][k] fp16 via 32x32 smem tiles.
__global__ __launch_bounds__(256) void cvt_wt(const float* __restrict__ W) {
    __shared__ __half t[32][33];
    const int n0 = blockIdx.x * 32;
    const int k0 = blockIdx.y * 32;
    const int c = threadIdx.x & 31;
    const int r0 = threadIdx.x >> 5;       // 0..7
    #pragma unroll
    for (int r = 0; r < 4; r++) {
        int row = r0 + r * 8;
        t[row][c] = __float2half_rn(W[(size_t)(k0 + row) * N3 + n0 + c]);
    }
    __syncthreads();
    #pragma unroll
    for (int r = 0; r < 4; r++) {
        int row = r0 + r * 8;               // n index within tile
        g_wt[(size_t)(n0 + row) * KK + k0 + c] = t[c][row];
    }
}
// sin/cos table: g_sc[i] = {sin(i), cos(i)} for i = s*128+d
__global__ __launch_bounds__(256) void sc_table() {
    int i = blockIdx.x * 256 + threadIdx.x;
    float sv, cv;
    sincosf((float)i, &sv, &cv);
    g_sc[i] = make_float2(sv, cv);
}

// ---------------------------------------------------------------------------
// Kernel 1: QKV GEMM via raw mma.sync m16n8k16 (fp32 acc), fused epilogue.
// Block 128x128, BK=32, 128 threads (4 warps, 2x2 grid, warp tile 64x64).
// Both A and B tiles stored row-major over [m|n][k] with LDA2=40 halves.
// 3-stage cp.async ring, one __syncthreads per iteration.
// smem: 3 * 20480 = 61440 B (epilogue Cs 64x132 fp32 = 33792 B reuses it).
// __launch_bounds__(128,3) -> 3 CTAs/SM (regs <= 170).
// ---------------------------------------------------------------------------
#define STG_H (2 * 128 * LDA2)             // halves per stage: 10240
#define GEMM_SMEM (3 * STG_H * 2)          // 61440 B

__device__ __forceinline__ void load_tiles(__half* As, __half* Bs,
                                           int m0, int n0, int kt, int tid) {
    #pragma unroll
    for (int i = 0; i < 4; i++) {          // A: 128 rows x 32 halves = 512 chunks
        int idx = tid + i * 128;
        int row = idx >> 2;
        int c8 = (idx & 3) << 3;
        cp_async16(As + row * LDA2 + c8, g_xh + (size_t)(m0 + row) * KK + kt + c8);
    }
    #pragma unroll
    for (int i = 0; i < 4; i++) {          // B: 128 n-rows x 32 k-halves
        int idx = tid + i * 128;
        int row = idx >> 2;
        int c8 = (idx & 3) << 3;
        cp_async16(Bs + row * LDA2 + c8, g_wt + (size_t)(n0 + row) * KK + kt + c8);
    }
}

__global__ __launch_bounds__(128, 3) void qkv_gemm(const float* __restrict__ bias) {
    extern __shared__ char smraw[];
    __half* stg[3] = { (__half*)smraw, (__half*)smraw + STG_H,
                       (__half*)smraw + 2 * STG_H };

    const int tid = threadIdx.x;
    const int wid = tid >> 5;
    const int lane = tid & 31;
    const int wm = wid & 1;                // m offset wm*64
    const int wn = wid >> 1;               // n offset wn*64
    const int g = lane >> 2;
    const int q = lane & 3;
    const int m0 = blockIdx.y * 128;
    const int n0 = blockIdx.x * 128;

    float s_[4][8][4];
    #pragma unroll
    for (int mf = 0; mf < 4; mf++)
        #pragma unroll
        for (int nf = 0; nf < 8; nf++)
            #pragma unroll
            for (int e = 0; e < 4; e++) s_[mf][nf][e] = 0.0f;

    load_tiles(stg[0], stg[0] + 128 * LDA2, m0, n0, 0, tid);
    cp_commit();
    load_tiles(stg[1], stg[1] + 128 * LDA2, m0, n0, 32, tid);
    cp_commit();

    const int NT = KK / 32;                // 64
    for (int t = 0; t < NT; t++) {
        const int s = t % 3;
        if (t == NT - 1) cp_wait<0>(); else cp_wait<1>();
        __syncthreads();

        if (t + 2 < NT) {
            const int sn = (t + 2) % 3;
            load_tiles(stg[sn], stg[sn] + 128 * LDA2, m0, n0, (t + 2) * 32, tid);
        }
        cp_commit();                       // one group per iteration

        const __half* As = stg[s];
        const __half* Bs = stg[s] + 128 * LDA2;
        #pragma unroll
        for (int kk = 0; kk < 32; kk += 16) {
            unsigned a[4][4];
            #pragma unroll
            for (int mf = 0; mf < 4; mf++) {
                const __half* ap = As + (wm * 64 + mf * 16 + g) * LDA2 + kk + q * 2;
                a[mf][0] = *(const unsigned*)(ap);
                a[mf][1] = *(const unsigned*)(ap + 8 * LDA2);
                a[mf][2] = *(const unsigned*)(ap + 8);
                a[mf][3] = *(const unsigned*)(ap + 8 * LDA2 + 8);
            }
            #pragma unroll
            for (int nf = 0; nf < 8; nf++) {
                const __half* bp = Bs + (wn * 64 + nf * 8 + g) * LDA2 + kk + q * 2;
                unsigned bf[2] = { *(const unsigned*)(bp), *(const unsigned*)(bp + 8) };
                #pragma unroll
                for (int mf = 0; mf < 4; mf++)
                    mma_f16(s_[mf][nf], a[mf], bf);
            }
        }
    }
    __syncthreads();

    // ---- Fused epilogue in two 64-row halves (Cs reuses stage smem) ----
    float* Cs = (float*)smraw;             // 64 x 132 fp32 = 33792 B
    const int which = n0 >> 11;            // 0=q, 1=k, 2=v
    const int h = (n0 & 2047) >> 7;
    const int b = m0 >> 11;
    const int s_base = m0 & 2047;

    #pragma unroll
    for (int half = 0; half < 2; half++) {
        if (wm == half) {
            #pragma unroll
            for (int mf = 0; mf < 4; mf++)
                #pragma unroll
                for (int nf = 0; nf < 8; nf++) {
                    int r0 = mf * 16 + g;
                    int cc = wn * 64 + nf * 8 + q * 2;
                    float2 c01 = { s_[mf][nf][0], s_[mf][nf][1] };
                    float2 c23 = { s_[mf][nf][2], s_[mf][nf][3] };
                    *(float2*)(Cs + (size_t)r0 * LDC + cc) = c01;
                    *(float2*)(Cs + (size_t)(r0 + 8) * LDC + cc) = c23;
                }
        }
        __syncthreads();

        if (which < 2) {
            __half* dstb = (which == 0 ? g_qh : g_kh) + ((size_t)(b * HH + h) * SS) * DD;
            const float scale = (which == 0) ? 0.08838834764831845f : 1.0f;
            #pragma unroll
            for (int i = 0; i < 16; i++) {
                int idx = tid + i * 128;       // 2048 float4 slots
                int row = idx >> 5;            // 0..63
                int c4 = (idx & 31) << 2;
                int s = s_base + half * 64 + row;
                float4 u = *(const float4*)(Cs + row * LDC + c4);
                float4 w = *(const float4*)(Cs + row * LDC + (c4 ^ 64));
                float4 bu = *(const float4*)(bias + n0 + c4);
                float4 bw = *(const float4*)(bias + n0 + (c4 ^ 64));
                u.x += bu.x; u.y += bu.y; u.z += bu.z; u.w += bu.w;
                w.x += bw.x; w.y += bw.y; w.z += bw.z; w.w += bw.w;
                float sgn = (c4 < 64) ? -1.0f : 1.0f;
                const float2* scp = g_sc + (size_t)s * DD + c4;
                float2 sc0 = scp[0], sc1 = scp[1], sc2 = scp[2], sc3 = scp[3];
                float r0 = (u.x * sc0.y + sgn * w.x * sc0.x) * scale;
                float r1 = (u.y * sc1.y + sgn * w.y * sc1.x) * scale;
                float r2 = (u.z * sc2.y + sgn * w.z * sc2.x) * scale;
                float r3 = (u.w * sc3.y + sgn * w.w * sc3.x) * scale;
                __half* dp = dstb + (size_t)s * DD + c4;
                *(__half2*)(dp) = __floats2half2_rn(r0, r1);
                *(__half2*)(dp + 2) = __floats2half2_rn(r2, r3);
            }
        } else {
            __half* dstb = g_vt + ((size_t)(b * HH + h) * DD) * SS + s_base + half * 64;
            #pragma unroll
            for (int i = 0; i < 16; i++) {
                int idx = tid + i * 128;
                int d = idx >> 4;              // 0..127
                int s4 = (idx & 15) << 2;      // 0..60
                float bv = bias[n0 + d];
                float v0 = Cs[(s4 + 0) * LDC + d] + bv;
                float v1 = Cs[(s4 + 1) * LDC + d] + bv;
                float v2 = Cs[(s4 + 2) * LDC + d] + bv;
                float v3 = Cs[(s4 + 3) * LDC + d] + bv;
                __half* dp = dstb + (size_t)d * SS + s4;
                *(__half2*)(dp) = __floats2half2_rn(v0, v1);
                *(__half2*)(dp + 2) = __floats2half2_rn(v2, v3);
            }
        }
        __syncthreads();
    }
}

// ---------------------------------------------------------------------------
// Kernel 3: flash attention via fp16 mma.sync (m16n8k16, fp32 accum).
// 512 threads (16 warps). BM=BN=128, D=128. P overwrites K smem. (Unchanged.)
// ---------------------------------------------------------------------------
#define LDQH2 136
#define ATT_SMEM (3 * 128 * LDQH2 * 2 + 1024 * 4)

__global__ __launch_bounds__(512, 1) void attn_tc(float* __restrict__ out) {
    extern __shared__ char smraw[];
    __half* Qs = (__half*)smraw;             // [128][136]
    __half* KP = Qs + 128 * LDQH2;           // K tile, later P tile
    __half* Vt = KP + 128 * LDQH2;           // V^T tile: [d][s]
    float* mpart = (float*)(Vt + 128 * LDQH2);
    float* lpart = mpart + 512;

    const int tid = threadIdx.x;
    const int wid = tid >> 5;
    const int lane = tid & 31;
    const int wm = wid & 3;
    const int wn = wid >> 2;
    const int g = lane >> 2;
    const int q = lane & 3;
    const int rbase = wm * 32;
    const int s0 = blockIdx.x * 128;
    const int h = blockIdx.y;
    const int b = blockIdx.z;

    const __half* qg = g_qh + ((size_t)(b * HH + h) * SS + s0) * DD;
    const __half* kg = g_kh + ((size_t)(b * HH + h) * SS) * DD;
    const __half* vtg = g_vt + ((size_t)(b * HH + h) * DD) * SS;

    #pragma unroll
    for (int i = 0; i < 4; i++) {
        int idx = tid + i * 512;
        int row = idx >> 4;
        int c8 = (idx & 15) << 3;
        cp_async16(Qs + row * LDQH2 + c8, qg + (size_t)row * DD + c8);
    }
    cp_commit();
    #pragma unroll
    for (int i = 0; i < 4; i++) {
        int idx = tid + i * 512;
        int row = idx >> 4;
        int c8 = (idx & 15) << 3;
        cp_async16(KP + row * LDQH2 + c8, kg + (size_t)row * DD + c8);
    }
    cp_commit();
    #pragma unroll
    for (int i = 0; i < 4; i++) {
        int idx = tid + i * 512;
        int row = idx >> 4;
        int c8 = (idx & 15) << 3;
        cp_async16(Vt + row * LDQH2 + c8, vtg + (size_t)row * SS + c8);
    }
    cp_commit();

    float o[2][4][4];
    #pragma unroll
    for (int mf = 0; mf < 2; mf++)
        #pragma unroll
        for (int nf = 0; nf < 4; nf++)
            #pragma unroll
            for (int e = 0; e < 4; e++) o[mf][nf][e] = 0.0f;
    float m_run[2][2] = {{-1e30f, -1e30f}, {-1e30f, -1e30f}};
    float l_run[2][2] = {{0.0f, 0.0f}, {0.0f, 0.0f}};

    for (int t = 0; t < SS / 128; t++) {
        cp_wait<1>();
        __syncthreads();

        float s_[2][4][4];
        #pragma unroll
        for (int mf = 0; mf < 2; mf++)
            #pragma unroll
            for (int nf = 0; nf < 4; nf++)
                #pragma unroll
                for (int e = 0; e < 4; e++) s_[mf][nf][e] = 0.0f;

        #pragma unroll
        for (int kk = 0; kk < 8; kk++) {
            unsigned a[2][4];
            #pragma unroll
            for (int mf = 0; mf < 2; mf++) {
                const __half* qp = Qs + (rbase + mf * 16 + g) * LDQH2 + kk * 16 + q * 2;
                a[mf][0] = *(const unsigned*)(qp);
                a[mf][1] = *(const unsigned*)(qp + 8 * LDQH2);
                a[mf][2] = *(const unsigned*)(qp + 8);
                a[mf][3] = *(const unsigned*)(qp + 8 * LDQH2 + 8);
            }
            #pragma unroll
            for (int nf = 0; nf < 4; nf++) {
                const __half* kp = KP + (wn * 32 + nf * 8 + g) * LDQH2 + kk * 16 + q * 2;
                unsigned bf[2] = { *(const unsigned*)(kp), *(const unsigned*)(kp + 8) };
                mma_f16(s_[0][nf], a[0], bf);
                mma_f16(s_[1][nf], a[1], bf);
            }
        }

        float lm[2][2] = {{-1e30f, -1e30f}, {-1e30f, -1e30f}};
        #pragma unroll
        for (int mf = 0; mf < 2; mf++)
            #pragma unroll
            for (int nf = 0; nf < 4; nf++) {
                lm[mf][0] = fmaxf(lm[mf][0], fmaxf(s_[mf][nf][0], s_[mf][nf][1]));
                lm[mf][1] = fmaxf(lm[mf][1], fmaxf(s_[mf][nf][2], s_[mf][nf][3]));
            }
        #pragma unroll
        for (int off = 1; off <= 2; off <<= 1)
            #pragma unroll
            for (int mf = 0; mf < 2; mf++)
                #pragma unroll
                for (int hf = 0; hf < 2; hf++)
                    lm[mf][hf] = fmaxf(lm[mf][hf],
                                       __shfl_xor_sync(0xffffffffu, lm[mf][hf], off));
        if (q == 0) {
            #pragma unroll
            for (int mf = 0; mf < 2; mf++)
                #pragma unroll
                for (int hf = 0; hf < 2; hf++)
                    mpart[wn * 128 + rbase + mf * 16 + g + hf * 8] = lm[mf][hf];
        }
        __syncthreads();

        float mnew[2][2], al[2][2];
        #pragma unroll
        for (int mf = 0; mf < 2; mf++)
            #pragma unroll
            for (int hf = 0; hf < 2; hf++) {
                int r = rbase + mf * 16 + g + hf * 8;
                float mv = fmaxf(fmaxf(mpart[r], mpart[128 + r]),
                                 fmaxf(mpart[256 + r], mpart[384 + r]));
                float mn = fmaxf(m_run[mf][hf], mv);
                al[mf][hf] = __expf(m_run[mf][hf] - mn);
                m_run[mf][hf] = mn;
                mnew[mf][hf] = mn;
            }
        float ls[2][2] = {{0.0f, 0.0f}, {0.0f, 0.0f}};
        #pragma unroll
        for (int mf = 0; mf < 2; mf++)
            #pragma unroll
            for (int nf = 0; nf < 4; nf++) {
                float p0 = __expf(s_[mf][nf][0] - mnew[mf][0]);
                float p1 = __expf(s_[mf][nf][1] - mnew[mf][0]);
                float p2 = __expf(s_[mf][nf][2] - mnew[mf][1]);
                float p3 = __expf(s_[mf][nf][3] - mnew[mf][1]);
                ls[mf][0] += p0 + p1;
                ls[mf][1] += p2 + p3;
                int col = wn * 32 + nf * 8 + q * 2;
                *(__half2*)(KP + (rbase + mf * 16 + g) * LDQH2 + col) =
                    __floats2half2_rn(p0, p1);
                *(__half2*)(KP + (rbase + mf * 16 + g + 8) * LDQH2 + col) =
                    __floats2half2_rn(p2, p3);
            }
        #pragma unroll
        for (int off = 1; off <= 2; off <<= 1)
            #pragma unroll
            for (int mf = 0; mf < 2; mf++)
                #pragma unroll
                for (int hf = 0; hf < 2; hf++)
                    ls[mf][hf] += __shfl_xor_sync(0xffffffffu, ls[mf][hf], off);
        if (q == 0) {
            #pragma unroll
            for (int mf = 0; mf < 2; mf++)
                #pragma unroll
                for (int hf = 0; hf < 2; hf++)
                    lpart[wn * 128 + rbase + mf * 16 + g + hf * 8] = ls[mf][hf];
        }
        cp_wait<0>();
        __syncthreads();

        #pragma unroll
        for (int mf = 0; mf < 2; mf++)
            #pragma unroll
            for (int hf = 0; hf < 2; hf++) {
                int r = rbase + mf * 16 + g + hf * 8;
                float lsum = lpart[r] + lpart[128 + r] + lpart[256 + r] + lpart[384 + r];
                l_run[mf][hf] = l_run[mf][hf] * al[mf][hf] + lsum;
            }
        #pragma unroll
        for (int mf = 0; mf < 2; mf++)
            #pragma unroll
            for (int nf = 0; nf < 4; nf++) {
                o[mf][nf][0] *= al[mf][0];
                o[mf][nf][1] *= al[mf][0];
                o[mf][nf][2] *= al[mf][1];
                o[mf][nf][3] *= al[mf][1];
            }

        #pragma unroll
        for (int kk = 0; kk < 8; kk++) {
            unsigned a[2][4];
            #pragma unroll
            for (int mf = 0; mf < 2; mf++) {
                const __half* pp = KP + (rbase + mf * 16 + g) * LDQH2 + kk * 16 + q * 2;
                a[mf][0] = *(const unsigned*)(pp);
                a[mf][1] = *(const unsigned*)(pp + 8 * LDQH2);
                a[mf][2] = *(const unsigned*)(pp + 8);
                a[mf][3] = *(const unsigned*)(pp + 8 * LDQH2 + 8);
            }
            #pragma unroll
            for (int nf = 0; nf < 4; nf++) {
                const __half* vp = Vt + (wn * 32 + nf * 8 + g) * LDQH2 + kk * 16 + q * 2;
                unsigned bf[2] = { *(const unsigned*)(vp), *(const unsigned*)(vp + 8) };
                mma_f16(o[0][nf], a[0], bf);
                mma_f16(o[1][nf], a[1], bf);
            }
        }
        __syncthreads();

        if (t + 1 < SS / 128) {
            const __half* kn = kg + (size_t)(t + 1) * 128 * DD;
            const __half* vn = vtg + (size_t)(t + 1) * 128;
            #pragma unroll
            for (int i = 0; i < 4; i++) {
                int idx = tid + i * 512;
                int row = idx >> 4;
                int c8 = (idx & 15) << 3;
                cp_async16(KP + row * LDQH2 + c8, kn + (size_t)row * DD + c8);
            }
            cp_commit();
            #pragma unroll
            for (int i = 0; i < 4; i++) {
                int idx = tid + i * 512;
                int row = idx >> 4;
                int c8 = (idx & 15) << 3;
                cp_async16(Vt + row * LDQH2 + c8, vn + (size_t)row * SS + c8);
            }
            cp_commit();
        }
    }

    float inv[2][2];
    #pragma unroll
    for (int mf = 0; mf < 2; mf++)
        #pragma unroll
        for (int hf = 0; hf < 2; hf++)
            inv[mf][hf] = 1.0f / l_run[mf][hf];

    #pragma unroll
    for (int mf = 0; mf < 2; mf++)
        #pragma unroll
        for (int nf = 0; nf < 4; nf++) {
            int col = wn * 32 + nf * 8 + q * 2;
            int row0 = s0 + rbase + mf * 16 + g;
            float2 w0 = { o[mf][nf][0] * inv[mf][0], o[mf][nf][1] * inv[mf][0] };
            float2 w1 = { o[mf][nf][2] * inv[mf][1], o[mf][nf][3] * inv[mf][1] };
            *(float2*)(out + ((size_t)(b * SS + row0) * HH + h) * DD + col) = w0;
            *(float2*)(out + ((size_t)(b * SS + row0 + 8) * HH + h) * DD + col) = w1;
        }
}

// ---------------------------------------------------------------------------
extern "C" void kernel_launch(void* const* d_in, const int* in_sizes, int n_in,
                              void* d_out, int out_size) {
    const float* x    = (const float*)d_in[0];
    const float* W    = (const float*)d_in[1];
    const float* bias = (const float*)d_in[2];
    float* out = (float*)d_out;

    cvt_x<<<(int)((size_t)MM * KK / 2048), 256>>>(x);
    dim3 gw(N3 / 32, KK / 32);
    cvt_wt<<<gw, 256>>>(W);
    sc_table<<<SS * DD / 256, 256>>>();

    cudaFuncSetAttribute(qkv_gemm, cudaFuncAttributeMaxDynamicSharedMemorySize, GEMM_SMEM);
    dim3 g1(N3 / 128, MM / 128);
    qkv_gemm<<<g1, 128, GEMM_SMEM>>>(bias);

    cudaFuncSetAttribute(attn_tc, cudaFuncAttributeMaxDynamicSharedMemorySize, ATT_SMEM);
    dim3 g3(SS / 128, HH, BB);
    attn_tc<<<g3, 512, ATT_SMEM>>>(out);
}

// round 11
// speedup vs baseline: 1.2035x; 1.0911x over previous
#include <cuda_runtime.h>
#include <mma.h>
#include <math.h>
#include <stdint.h>
#include <cuda_fp16.h>

#define BB 2
#define SS 2048
#define EE 2048
#define HH 16
#define DD 128
#define N3 6144            // 3*EE
#define MM (BB*SS)         // 4096
#define KK EE              // 2048

#define LDA2 40            // smem row stride (halves) for A and B(nk) tiles
#define LDC  132           // epilogue staging stride (floats)

// Scratch (static device globals — allowed; no runtime allocation)
__device__ __half g_xh [(size_t)MM * KK];           // X in fp16 (RN)
__device__ __half g_wt [(size_t)N3 * KK];           // W^T in fp16 (RN), [n][k]
__device__ float2 g_sc [(size_t)SS * DD];           // sin/cos table for t = s*128+d
__device__ __half g_qh [(size_t)BB * HH * SS * DD]; // Q roped+scaled, [b][h][s][d]
__device__ __half g_kh [(size_t)BB * HH * SS * DD]; // K roped,        [b][h][s][d]
__device__ __half g_vt [(size_t)BB * HH * DD * SS]; // V transposed,   [b][h][d][s]

// ---------------------------------------------------------------------------
// Helpers
// ---------------------------------------------------------------------------
__device__ __forceinline__ void cp_async16(void* dst_smem, const void* src_gmem) {
    unsigned int dst = (unsigned int)__cvta_generic_to_shared(dst_smem);
    asm volatile("cp.async.cg.shared.global [%0], [%1], 16;\n" :: "r"(dst), "l"(src_gmem));
}
__device__ __forceinline__ void cp_commit() {
    asm volatile("cp.async.commit_group;\n" ::: "memory");
}
template <int N>
__device__ __forceinline__ void cp_wait() {
    asm volatile("cp.async.wait_group %0;\n" :: "n"(N) : "memory");
}
// mma.sync m16n8k16 fp16 -> fp32, documented lane mapping
__device__ __forceinline__ void mma_f16(float* c, const unsigned* a, const unsigned* b) {
    asm volatile(
        "mma.sync.aligned.m16n8k16.row.col.f32.f16.f16.f32 "
        "{%0,%1,%2,%3}, {%4,%5,%6,%7}, {%8,%9}, {%0,%1,%2,%3};"
        : "+f"(c[0]), "+f"(c[1]), "+f"(c[2]), "+f"(c[3])
        : "r"(a[0]), "r"(a[1]), "r"(a[2]), "r"(a[3]), "r"(b[0]), "r"(b[1]));
}
// ldmatrix.x4: 4 8x8 b16 matrices; matrix i sourced from lanes 8i..8i+7.
__device__ __forceinline__ void ldsm_x4(unsigned* r, const __half* p) {
    unsigned addr = (unsigned)__cvta_generic_to_shared(p);
    asm volatile("ldmatrix.sync.aligned.m8n8.x4.shared.b16 {%0,%1,%2,%3}, [%4];"
                 : "=r"(r[0]), "=r"(r[1]), "=r"(r[2]), "=r"(r[3]) : "r"(addr));
}

// ---------------------------------------------------------------------------
// Prep kernels
// ---------------------------------------------------------------------------
__global__ __launch_bounds__(256) void cvt_x(const float* __restrict__ X) {
    size_t i = ((size_t)blockIdx.x * 256 + threadIdx.x) * 8;
    float4 v0 = *(const float4*)(X + i);
    float4 v1 = *(const float4*)(X + i + 4);
    __half2 h[4] = { __floats2half2_rn(v0.x, v0.y), __floats2half2_rn(v0.z, v0.w),
                     __floats2half2_rn(v1.x, v1.y), __floats2half2_rn(v1.z, v1.w) };
    *(uint4*)(g_xh + i) = *(uint4*)h;
}
// Transpose W [k][n] fp32 -> g_wt [n][k] fp16 via 32x32 smem tiles.
__global__ __launch_bounds__(256) void cvt_wt(const float* __restrict__ W) {
    __shared__ __half t[32][33];
    const int n0 = blockIdx.x * 32;
    const int k0 = blockIdx.y * 32;
    const int c = threadIdx.x & 31;
    const int r0 = threadIdx.x >> 5;       // 0..7
    #pragma unroll
    for (int r = 0; r < 4; r++) {
        int row = r0 + r * 8;
        t[row][c] = __float2half_rn(W[(size_t)(k0 + row) * N3 + n0 + c]);
    }
    __syncthreads();
    #pragma unroll
    for (int r = 0; r < 4; r++) {
        int row = r0 + r * 8;               // n index within tile
        g_wt[(size_t)(n0 + row) * KK + k0 + c] = t[c][row];
    }
}
// sin/cos table: g_sc[i] = {sin(i), cos(i)} for i = s*128+d
__global__ __launch_bounds__(256) void sc_table() {
    int i = blockIdx.x * 256 + threadIdx.x;
    float sv, cv;
    sincosf((float)i, &sv, &cv);
    g_sc[i] = make_float2(sv, cv);
}

// ---------------------------------------------------------------------------
// Kernel 1: QKV GEMM via raw mma.sync m16n8k16 (fp32 acc) + ldmatrix.x4
// fragment loads. Block 128x128, BK=32, 128 threads (4 warps, warp 64x64).
// 3-stage cp.async ring, one __syncthreads per iteration, fused epilogue.
// ---------------------------------------------------------------------------
#define STG_H (2 * 128 * LDA2)             // halves per stage: 10240
#define GEMM_SMEM (3 * STG_H * 2)          // 61440 B

__device__ __forceinline__ void load_tiles(__half* As, __half* Bs,
                                           int m0, int n0, int kt, int tid) {
    #pragma unroll
    for (int i = 0; i < 4; i++) {          // A: 128 rows x 32 halves = 512 chunks
        int idx = tid + i * 128;
        int row = idx >> 2;
        int c8 = (idx & 3) << 3;
        cp_async16(As + row * LDA2 + c8, g_xh + (size_t)(m0 + row) * KK + kt + c8);
    }
    #pragma unroll
    for (int i = 0; i < 4; i++) {          // B: 128 n-rows x 32 k-halves
        int idx = tid + i * 128;
        int row = idx >> 2;
        int c8 = (idx & 3) << 3;
        cp_async16(Bs + row * LDA2 + c8, g_wt + (size_t)(n0 + row) * KK + kt + c8);
    }
}

__global__ __launch_bounds__(128, 3) void qkv_gemm(const float* __restrict__ bias) {
    extern __shared__ char smraw[];
    __half* stg[3] = { (__half*)smraw, (__half*)smraw + STG_H,
                       (__half*)smraw + 2 * STG_H };

    const int tid = threadIdx.x;
    const int wid = tid >> 5;
    const int lane = tid & 31;
    const int wm = wid & 1;                // m offset wm*64
    const int wn = wid >> 1;               // n offset wn*64
    const int g = lane >> 2;
    const int q = lane & 3;
    const int m0 = blockIdx.y * 128;
    const int n0 = blockIdx.x * 128;

    // ldmatrix lane->address components
    const int arow = lane & 15;             // A: rows 0-15
    const int akadd = (lane >> 4) << 3;     // A: k offset 0/8
    const int brow = (lane & 7) + ((lane >> 4) << 3);  // B: n rows
    const int bkadd = ((lane >> 3) & 1) << 3;          // B: k offset 0/8

    float s_[4][8][4];
    #pragma unroll
    for (int mf = 0; mf < 4; mf++)
        #pragma unroll
        for (int nf = 0; nf < 8; nf++)
            #pragma unroll
            for (int e = 0; e < 4; e++) s_[mf][nf][e] = 0.0f;

    load_tiles(stg[0], stg[0] + 128 * LDA2, m0, n0, 0, tid);
    cp_commit();
    load_tiles(stg[1], stg[1] + 128 * LDA2, m0, n0, 32, tid);
    cp_commit();

    const int NT = KK / 32;                // 64
    for (int t = 0; t < NT; t++) {
        const int s = t % 3;
        if (t == NT - 1) cp_wait<0>(); else cp_wait<1>();
        __syncthreads();

        if (t + 2 < NT) {
            const int sn = (t + 2) % 3;
            load_tiles(stg[sn], stg[sn] + 128 * LDA2, m0, n0, (t + 2) * 32, tid);
        }
        cp_commit();                       // one group per iteration

        const __half* As = stg[s];
        const __half* Bs = stg[s] + 128 * LDA2;
        #pragma unroll
        for (int kk = 0; kk < 32; kk += 16) {
            unsigned a[4][4];
            #pragma unroll
            for (int mf = 0; mf < 4; mf++)
                ldsm_x4(a[mf], As + (wm * 64 + mf * 16 + arow) * LDA2 + kk + akadd);
            unsigned b4[4][4];
            #pragma unroll
            for (int bi = 0; bi < 4; bi++)
                ldsm_x4(b4[bi], Bs + (wn * 64 + bi * 16 + brow) * LDA2 + kk + bkadd);
            #pragma unroll
            for (int nf = 0; nf < 8; nf++) {
                const unsigned* bp = b4[nf >> 1] + (nf & 1) * 2;
                #pragma unroll
                for (int mf = 0; mf < 4; mf++)
                    mma_f16(s_[mf][nf], a[mf], bp);
            }
        }
    }
    __syncthreads();

    // ---- Fused epilogue in two 64-row halves (Cs reuses stage smem) ----
    float* Cs = (float*)smraw;             // 64 x 132 fp32 = 33792 B
    const int which = n0 >> 11;            // 0=q, 1=k, 2=v
    const int h = (n0 & 2047) >> 7;
    const int b = m0 >> 11;
    const int s_base = m0 & 2047;

    #pragma unroll
    for (int half = 0; half < 2; half++) {
        if (wm == half) {
            #pragma unroll
            for (int mf = 0; mf < 4; mf++)
                #pragma unroll
                for (int nf = 0; nf < 8; nf++) {
                    int r0 = mf * 16 + g;
                    int cc = wn * 64 + nf * 8 + q * 2;
                    float2 c01 = { s_[mf][nf][0], s_[mf][nf][1] };
                    float2 c23 = { s_[mf][nf][2], s_[mf][nf][3] };
                    *(float2*)(Cs + (size_t)r0 * LDC + cc) = c01;
                    *(float2*)(Cs + (size_t)(r0 + 8) * LDC + cc) = c23;
                }
        }
        __syncthreads();

        if (which < 2) {
            __half* dstb = (which == 0 ? g_qh : g_kh) + ((size_t)(b * HH + h) * SS) * DD;
            const float scale = (which == 0) ? 0.08838834764831845f : 1.0f;
            #pragma unroll
            for (int i = 0; i < 16; i++) {
                int idx = tid + i * 128;       // 2048 float4 slots
                int row = idx >> 5;            // 0..63
                int c4 = (idx & 31) << 2;
                int s = s_base + half * 64 + row;
                float4 u = *(const float4*)(Cs + row * LDC + c4);
                float4 w = *(const float4*)(Cs + row * LDC + (c4 ^ 64));
                float4 bu = *(const float4*)(bias + n0 + c4);
                float4 bw = *(const float4*)(bias + n0 + (c4 ^ 64));
                u.x += bu.x; u.y += bu.y; u.z += bu.z; u.w += bu.w;
                w.x += bw.x; w.y += bw.y; w.z += bw.z; w.w += bw.w;
                float sgn = (c4 < 64) ? -1.0f : 1.0f;
                const float2* scp = g_sc + (size_t)s * DD + c4;
                float2 sc0 = scp[0], sc1 = scp[1], sc2 = scp[2], sc3 = scp[3];
                float r0 = (u.x * sc0.y + sgn * w.x * sc0.x) * scale;
                float r1 = (u.y * sc1.y + sgn * w.y * sc1.x) * scale;
                float r2 = (u.z * sc2.y + sgn * w.z * sc2.x) * scale;
                float r3 = (u.w * sc3.y + sgn * w.w * sc3.x) * scale;
                __half* dp = dstb + (size_t)s * DD + c4;
                *(__half2*)(dp) = __floats2half2_rn(r0, r1);
                *(__half2*)(dp + 2) = __floats2half2_rn(r2, r3);
            }
        } else {
            __half* dstb = g_vt + ((size_t)(b * HH + h) * DD) * SS + s_base + half * 64;
            #pragma unroll
            for (int i = 0; i < 16; i++) {
                int idx = tid + i * 128;
                int d = idx >> 4;              // 0..127
                int s4 = (idx & 15) << 2;      // 0..60
                float bv = bias[n0 + d];
                float v0 = Cs[(s4 + 0) * LDC + d] + bv;
                float v1 = Cs[(s4 + 1) * LDC + d] + bv;
                float v2 = Cs[(s4 + 2) * LDC + d] + bv;
                float v3 = Cs[(s4 + 3) * LDC + d] + bv;
                __half* dp = dstb + (size_t)d * SS + s4;
                *(__half2*)(dp) = __floats2half2_rn(v0, v1);
                *(__half2*)(dp + 2) = __floats2half2_rn(v2, v3);
            }
        }
        __syncthreads();
    }
}

// ---------------------------------------------------------------------------
// Kernel 3: flash attention via fp16 mma.sync + ldmatrix.x4 fragment loads.
// 512 threads (16 warps). BM=BN=128, D=128. P overwrites K smem.
// ---------------------------------------------------------------------------
#define LDQH2 136
#define ATT_SMEM (3 * 128 * LDQH2 * 2 + 1024 * 4)

__global__ __launch_bounds__(512, 1) void attn_tc(float* __restrict__ out) {
    extern __shared__ char smraw[];
    __half* Qs = (__half*)smraw;             // [128][136]
    __half* KP = Qs + 128 * LDQH2;           // K tile, later P tile
    __half* Vt = KP + 128 * LDQH2;           // V^T tile: [d][s]
    float* mpart = (float*)(Vt + 128 * LDQH2);
    float* lpart = mpart + 512;

    const int tid = threadIdx.x;
    const int wid = tid >> 5;
    const int lane = tid & 31;
    const int wm = wid & 3;
    const int wn = wid >> 2;
    const int g = lane >> 2;
    const int q = lane & 3;
    const int rbase = wm * 32;
    const int s0 = blockIdx.x * 128;
    const int h = blockIdx.y;
    const int b = blockIdx.z;

    const int arow = lane & 15;
    const int akadd = (lane >> 4) << 3;
    const int brow = (lane & 7) + ((lane >> 4) << 3);
    const int bkadd = ((lane >> 3) & 1) << 3;

    const __half* qg = g_qh + ((size_t)(b * HH + h) * SS + s0) * DD;
    const __half* kg = g_kh + ((size_t)(b * HH + h) * SS) * DD;
    const __half* vtg = g_vt + ((size_t)(b * HH + h) * DD) * SS;

    #pragma unroll
    for (int i = 0; i < 4; i++) {
        int idx = tid + i * 512;
        int row = idx >> 4;
        int c8 = (idx & 15) << 3;
        cp_async16(Qs + row * LDQH2 + c8, qg + (size_t)row * DD + c8);
    }
    cp_commit();
    #pragma unroll
    for (int i = 0; i < 4; i++) {
        int idx = tid + i * 512;
        int row = idx >> 4;
        int c8 = (idx & 15) << 3;
        cp_async16(KP + row * LDQH2 + c8, kg + (size_t)row * DD + c8);
    }
    cp_commit();
    #pragma unroll
    for (int i = 0; i < 4; i++) {
        int idx = tid + i * 512;
        int row = idx >> 4;
        int c8 = (idx & 15) << 3;
        cp_async16(Vt + row * LDQH2 + c8, vtg + (size_t)row * SS + c8);
    }
    cp_commit();

    float o[2][4][4];
    #pragma unroll
    for (int mf = 0; mf < 2; mf++)
        #pragma unroll
        for (int nf = 0; nf < 4; nf++)
            #pragma unroll
            for (int e = 0; e < 4; e++) o[mf][nf][e] = 0.0f;
    float m_run[2][2] = {{-1e30f, -1e30f}, {-1e30f, -1e30f}};
    float l_run[2][2] = {{0.0f, 0.0f}, {0.0f, 0.0f}};

    for (int t = 0; t < SS / 128; t++) {
        cp_wait<1>();
        __syncthreads();

        float s_[2][4][4];
        #pragma unroll
        for (int mf = 0; mf < 2; mf++)
            #pragma unroll
            for (int nf = 0; nf < 4; nf++)
                #pragma unroll
                for (int e = 0; e < 4; e++) s_[mf][nf][e] = 0.0f;

        #pragma unroll
        for (int kk = 0; kk < 8; kk++) {
            unsigned a[2][4];
            #pragma unroll
            for (int mf = 0; mf < 2; mf++)
                ldsm_x4(a[mf], Qs + (rbase + mf * 16 + arow) * LDQH2 + kk * 16 + akadd);
            unsigned b4[2][4];
            #pragma unroll
            for (int bi = 0; bi < 2; bi++)
                ldsm_x4(b4[bi], KP + (wn * 32 + bi * 16 + brow) * LDQH2 + kk * 16 + bkadd);
            #pragma unroll
            for (int nf = 0; nf < 4; nf++) {
                const unsigned* bp = b4[nf >> 1] + (nf & 1) * 2;
                mma_f16(s_[0][nf], a[0], bp);
                mma_f16(s_[1][nf], a[1], bp);
            }
        }

        float lm[2][2] = {{-1e30f, -1e30f}, {-1e30f, -1e30f}};
        #pragma unroll
        for (int mf = 0; mf < 2; mf++)
            #pragma unroll
            for (int nf = 0; nf < 4; nf++) {
                lm[mf][0] = fmaxf(lm[mf][0], fmaxf(s_[mf][nf][0], s_[mf][nf][1]));
                lm[mf][1] = fmaxf(lm[mf][1], fmaxf(s_[mf][nf][2], s_[mf][nf][3]));
            }
        #pragma unroll
        for (int off = 1; off <= 2; off <<= 1)
            #pragma unroll
            for (int mf = 0; mf < 2; mf++)
                #pragma unroll
                for (int hf = 0; hf < 2; hf++)
                    lm[mf][hf] = fmaxf(lm[mf][hf],
                                       __shfl_xor_sync(0xffffffffu, lm[mf][hf], off));
        if (q == 0) {
            #pragma unroll
            for (int mf = 0; mf < 2; mf++)
                #pragma unroll
                for (int hf = 0; hf < 2; hf++)
                    mpart[wn * 128 + rbase + mf * 16 + g + hf * 8] = lm[mf][hf];
        }
        __syncthreads();

        float mnew[2][2], al[2][2];
        #pragma unroll
        for (int mf = 0; mf < 2; mf++)
            #pragma unroll
            for (int hf = 0; hf < 2; hf++) {
                int r = rbase + mf * 16 + g + hf * 8;
                float mv = fmaxf(fmaxf(mpart[r], mpart[128 + r]),
                                 fmaxf(mpart[256 + r], mpart[384 + r]));
                float mn = fmaxf(m_run[mf][hf], mv);
                al[mf][hf] = __expf(m_run[mf][hf] - mn);
                m_run[mf][hf] = mn;
                mnew[mf][hf] = mn;
            }
        float ls[2][2] = {{0.0f, 0.0f}, {0.0f, 0.0f}};
        #pragma unroll
        for (int mf = 0; mf < 2; mf++)
            #pragma unroll
            for (int nf = 0; nf < 4; nf++) {
                float p0 = __expf(s_[mf][nf][0] - mnew[mf][0]);
                float p1 = __expf(s_[mf][nf][1] - mnew[mf][0]);
                float p2 = __expf(s_[mf][nf][2] - mnew[mf][1]);
                float p3 = __expf(s_[mf][nf][3] - mnew[mf][1]);
                ls[mf][0] += p0 + p1;
                ls[mf][1] += p2 + p3;
                int col = wn * 32 + nf * 8 + q * 2;
                *(__half2*)(KP + (rbase + mf * 16 + g) * LDQH2 + col) =
                    __floats2half2_rn(p0, p1);
                *(__half2*)(KP + (rbase + mf * 16 + g + 8) * LDQH2 + col) =
                    __floats2half2_rn(p2, p3);
            }
        #pragma unroll
        for (int off = 1; off <= 2; off <<= 1)
            #pragma unroll
            for (int mf = 0; mf < 2; mf++)
                #pragma unroll
                for (int hf = 0; hf < 2; hf++)
                    ls[mf][hf] += __shfl_xor_sync(0xffffffffu, ls[mf][hf], off);
        if (q == 0) {
            #pragma unroll
            for (int mf = 0; mf < 2; mf++)
                #pragma unroll
                for (int hf = 0; hf < 2; hf++)
                    lpart[wn * 128 + rbase + mf * 16 + g + hf * 8] = ls[mf][hf];
        }
        cp_wait<0>();
        __syncthreads();

        #pragma unroll
        for (int mf = 0; mf < 2; mf++)
            #pragma unroll
            for (int hf = 0; hf < 2; hf++) {
                int r = rbase + mf * 16 + g + hf * 8;
                float lsum = lpart[r] + lpart[128 + r] + lpart[256 + r] + lpart[384 + r];
                l_run[mf][hf] = l_run[mf][hf] * al[mf][hf] + lsum;
            }
        #pragma unroll
        for (int mf = 0; mf < 2; mf++)
            #pragma unroll
            for (int nf = 0; nf < 4; nf++) {
                o[mf][nf][0] *= al[mf][0];
                o[mf][nf][1] *= al[mf][0];
                o[mf][nf][2] *= al[mf][1];
                o[mf][nf][3] *= al[mf][1];
            }

        #pragma unroll
        for (int kk = 0; kk < 8; kk++) {
            unsigned a[2][4];
            #pragma unroll
            for (int mf = 0; mf < 2; mf++)
                ldsm_x4(a[mf], KP + (rbase + mf * 16 + arow) * LDQH2 + kk * 16 + akadd);
            unsigned b4[2][4];
            #pragma unroll
            for (int bi = 0; bi < 2; bi++)
                ldsm_x4(b4[bi], Vt + (wn * 32 + bi * 16 + brow) * LDQH2 + kk * 16 + bkadd);
            #pragma unroll
            for (int nf = 0; nf < 4; nf++) {
                const unsigned* bp = b4[nf >> 1] + (nf & 1) * 2;
                mma_f16(o[0][nf], a[0], bp);
                mma_f16(o[1][nf], a[1], bp);
            }
        }
        __syncthreads();

        if (t + 1 < SS / 128) {
            const __half* kn = kg + (size_t)(t + 1) * 128 * DD;
            const __half* vn = vtg + (size_t)(t + 1) * 128;
            #pragma unroll
            for (int i = 0; i < 4; i++) {
                int idx = tid + i * 512;
                int row = idx >> 4;
                int c8 = (idx & 15) << 3;
                cp_async16(KP + row * LDQH2 + c8, kn + (size_t)row * DD + c8);
            }
            cp_commit();
            #pragma unroll
            for (int i = 0; i < 4; i++) {
                int idx = tid + i * 512;
                int row = idx >> 4;
                int c8 = (idx & 15) << 3;
                cp_async16(Vt + row * LDQH2 + c8, vn + (size_t)row * SS + c8);
            }
            cp_commit();
        }
    }

    float inv[2][2];
    #pragma unroll
    for (int mf = 0; mf < 2; mf++)
        #pragma unroll
        for (int hf = 0; hf < 2; hf++)
            inv[mf][hf] = 1.0f / l_run[mf][hf];

    #pragma unroll
    for (int mf = 0; mf < 2; mf++)
        #pragma unroll
        for (int nf = 0; nf < 4; nf++) {
            int col = wn * 32 + nf * 8 + q * 2;
            int row0 = s0 + rbase + mf * 16 + g;
            float2 w0 = { o[mf][nf][0] * inv[mf][0], o[mf][nf][1] * inv[mf][0] };
            float2 w1 = { o[mf][nf][2] * inv[mf][1], o[mf][nf][3] * inv[mf][1] };
            *(float2*)(out + ((size_t)(b * SS + row0) * HH + h) * DD + col) = w0;
            *(float2*)(out + ((size_t)(b * SS + row0 + 8) * HH + h) * DD + col) = w1;
        }
}

// ---------------------------------------------------------------------------
extern "C" void kernel_launch(void* const* d_in, const int* in_sizes, int n_in,
                              void* d_out, int out_size) {
    const float* x    = (const float*)d_in[0];
    const float* W    = (const float*)d_in[1];
    const float* bias = (const float*)d_in[2];
    float* out = (float*)d_out;

    cvt_x<<<(int)((size_t)MM * KK / 2048), 256>>>(x);
    dim3 gw(N3 / 32, KK / 32);
    cvt_wt<<<gw, 256>>>(W);
    sc_table<<<SS * DD / 256, 256>>>();

    cudaFuncSetAttribute(qkv_gemm, cudaFuncAttributeMaxDynamicSharedMemorySize, GEMM_SMEM);
    dim3 g1(N3 / 128, MM / 128);
    qkv_gemm<<<g1, 128, GEMM_SMEM>>>(bias);

    cudaFuncSetAttribute(attn_tc, cudaFuncAttributeMaxDynamicSharedMemorySize, ATT_SMEM);
    dim3 g3(SS / 128, HH, BB);
    attn_tc<<<g3, 512, ATT_SMEM>>>(out);
}

// round 12
// speedup vs baseline: 1.3542x; 1.1253x over previous
#include <cuda_runtime.h>
#include <mma.h>
#include <math.h>
#include <stdint.h>
#include <cuda_fp16.h>

#define BB 2
#define SS 2048
#define EE 2048
#define HH 16
#define DD 128
#define N3 6144            // 3*EE
#define MM (BB*SS)         // 4096
#define KK EE              // 2048

#define LDA2 40            // GEMM smem row stride (halves) for A and B(nk) tiles
#define LDC  132           // GEMM epilogue staging stride (floats)

// Scratch (static device globals — allowed; no runtime allocation)
__device__ __half g_xh [(size_t)MM * KK];           // X in fp16 (RN)
__device__ __half g_wt [(size_t)N3 * KK];           // W^T in fp16 (RN), [n][k]
__device__ float2 g_sc [(size_t)SS * DD];           // sin/cos table for t = s*128+d
__device__ __half g_qh [(size_t)BB * HH * SS * DD]; // Q roped+scaled, [b][h][s][d]
__device__ __half g_kh [(size_t)BB * HH * SS * DD]; // K roped,        [b][h][s][d]
__device__ __half g_vt [(size_t)BB * HH * DD * SS]; // V transposed,   [b][h][d][s]

// ---------------------------------------------------------------------------
// Helpers
// ---------------------------------------------------------------------------
__device__ __forceinline__ void cp_async16(void* dst_smem, const void* src_gmem) {
    unsigned int dst = (unsigned int)__cvta_generic_to_shared(dst_smem);
    asm volatile("cp.async.cg.shared.global [%0], [%1], 16;\n" :: "r"(dst), "l"(src_gmem));
}
__device__ __forceinline__ void cp_commit() {
    asm volatile("cp.async.commit_group;\n" ::: "memory");
}
template <int N>
__device__ __forceinline__ void cp_wait() {
    asm volatile("cp.async.wait_group %0;\n" :: "n"(N) : "memory");
}
// mma.sync m16n8k16 fp16 -> fp32, documented lane mapping
__device__ __forceinline__ void mma_f16(float* c, const unsigned* a, const unsigned* b) {
    asm volatile(
        "mma.sync.aligned.m16n8k16.row.col.f32.f16.f16.f32 "
        "{%0,%1,%2,%3}, {%4,%5,%6,%7}, {%8,%9}, {%0,%1,%2,%3};"
        : "+f"(c[0]), "+f"(c[1]), "+f"(c[2]), "+f"(c[3])
        : "r"(a[0]), "r"(a[1]), "r"(a[2]), "r"(a[3]), "r"(b[0]), "r"(b[1]));
}
// ldmatrix.x4: 4 8x8 b16 matrices; matrix i sourced from lanes 8i..8i+7.
__device__ __forceinline__ void ldsm_x4(unsigned* r, const __half* p) {
    unsigned addr = (unsigned)__cvta_generic_to_shared(p);
    asm volatile("ldmatrix.sync.aligned.m8n8.x4.shared.b16 {%0,%1,%2,%3}, [%4];"
                 : "=r"(r[0]), "=r"(r[1]), "=r"(r[2]), "=r"(r[3]) : "r"(addr));
}

// ---------------------------------------------------------------------------
// Prep kernels
// ---------------------------------------------------------------------------
__global__ __launch_bounds__(256) void cvt_x(const float* __restrict__ X) {
    size_t i = ((size_t)blockIdx.x * 256 + threadIdx.x) * 8;
    float4 v0 = *(const float4*)(X + i);
    float4 v1 = *(const float4*)(X + i + 4);
    __half2 h[4] = { __floats2half2_rn(v0.x, v0.y), __floats2half2_rn(v0.z, v0.w),
                     __floats2half2_rn(v1.x, v1.y), __floats2half2_rn(v1.z, v1.w) };
    *(uint4*)(g_xh + i) = *(uint4*)h;
}
// Transpose W [k][n] fp32 -> g_wt [n][k] fp16 via 32x32 smem tiles.
__global__ __launch_bounds__(256) void cvt_wt(const float* __restrict__ W) {
    __shared__ __half t[32][33];
    const int n0 = blockIdx.x * 32;
    const int k0 = blockIdx.y * 32;
    const int c = threadIdx.x & 31;
    const int r0 = threadIdx.x >> 5;       // 0..7
    #pragma unroll
    for (int r = 0; r < 4; r++) {
        int row = r0 + r * 8;
        t[row][c] = __float2half_rn(W[(size_t)(k0 + row) * N3 + n0 + c]);
    }
    __syncthreads();
    #pragma unroll
    for (int r = 0; r < 4; r++) {
        int row = r0 + r * 8;               // n index within tile
        g_wt[(size_t)(n0 + row) * KK + k0 + c] = t[c][row];
    }
}
// sin/cos table: g_sc[i] = {sin(i), cos(i)} for i = s*128+d
__global__ __launch_bounds__(256) void sc_table() {
    int i = blockIdx.x * 256 + threadIdx.x;
    float sv, cv;
    sincosf((float)i, &sv, &cv);
    g_sc[i] = make_float2(sv, cv);
}

// ---------------------------------------------------------------------------
// Kernel 1: QKV GEMM via raw mma.sync m16n8k16 (fp32 acc) + ldmatrix.x4
// fragment loads. Block 128x128, BK=32, 128 threads (4 warps, warp 64x64).
// 3-stage cp.async ring, one __syncthreads per iteration, fused epilogue.
// (Unchanged from R11.)
// ---------------------------------------------------------------------------
#define STG_H (2 * 128 * LDA2)             // halves per stage: 10240
#define GEMM_SMEM (3 * STG_H * 2)          // 61440 B

__device__ __forceinline__ void load_tiles(__half* As, __half* Bs,
                                           int m0, int n0, int kt, int tid) {
    #pragma unroll
    for (int i = 0; i < 4; i++) {          // A: 128 rows x 32 halves = 512 chunks
        int idx = tid + i * 128;
        int row = idx >> 2;
        int c8 = (idx & 3) << 3;
        cp_async16(As + row * LDA2 + c8, g_xh + (size_t)(m0 + row) * KK + kt + c8);
    }
    #pragma unroll
    for (int i = 0; i < 4; i++) {          // B: 128 n-rows x 32 k-halves
        int idx = tid + i * 128;
        int row = idx >> 2;
        int c8 = (idx & 3) << 3;
        cp_async16(Bs + row * LDA2 + c8, g_wt + (size_t)(n0 + row) * KK + kt + c8);
    }
}

__global__ __launch_bounds__(128, 3) void qkv_gemm(const float* __restrict__ bias) {
    extern __shared__ char smraw[];
    __half* stg[3] = { (__half*)smraw, (__half*)smraw + STG_H,
                       (__half*)smraw + 2 * STG_H };

    const int tid = threadIdx.x;
    const int wid = tid >> 5;
    const int lane = tid & 31;
    const int wm = wid & 1;                // m offset wm*64
    const int wn = wid >> 1;               // n offset wn*64
    const int g = lane >> 2;
    const int q = lane & 3;
    const int m0 = blockIdx.y * 128;
    const int n0 = blockIdx.x * 128;

    const int arow = lane & 15;
    const int akadd = (lane >> 4) << 3;
    const int brow = (lane & 7) + ((lane >> 4) << 3);
    const int bkadd = ((lane >> 3) & 1) << 3;

    float s_[4][8][4];
    #pragma unroll
    for (int mf = 0; mf < 4; mf++)
        #pragma unroll
        for (int nf = 0; nf < 8; nf++)
            #pragma unroll
            for (int e = 0; e < 4; e++) s_[mf][nf][e] = 0.0f;

    load_tiles(stg[0], stg[0] + 128 * LDA2, m0, n0, 0, tid);
    cp_commit();
    load_tiles(stg[1], stg[1] + 128 * LDA2, m0, n0, 32, tid);
    cp_commit();

    const int NT = KK / 32;                // 64
    for (int t = 0; t < NT; t++) {
        const int s = t % 3;
        if (t == NT - 1) cp_wait<0>(); else cp_wait<1>();
        __syncthreads();

        if (t + 2 < NT) {
            const int sn = (t + 2) % 3;
            load_tiles(stg[sn], stg[sn] + 128 * LDA2, m0, n0, (t + 2) * 32, tid);
        }
        cp_commit();                       // one group per iteration

        const __half* As = stg[s];
        const __half* Bs = stg[s] + 128 * LDA2;
        #pragma unroll
        for (int kk = 0; kk < 32; kk += 16) {
            unsigned a[4][4];
            #pragma unroll
            for (int mf = 0; mf < 4; mf++)
                ldsm_x4(a[mf], As + (wm * 64 + mf * 16 + arow) * LDA2 + kk + akadd);
            unsigned b4[4][4];
            #pragma unroll
            for (int bi = 0; bi < 4; bi++)
                ldsm_x4(b4[bi], Bs + (wn * 64 + bi * 16 + brow) * LDA2 + kk + bkadd);
            #pragma unroll
            for (int nf = 0; nf < 8; nf++) {
                const unsigned* bp = b4[nf >> 1] + (nf & 1) * 2;
                #pragma unroll
                for (int mf = 0; mf < 4; mf++)
                    mma_f16(s_[mf][nf], a[mf], bp);
            }
        }
    }
    __syncthreads();

    // ---- Fused epilogue in two 64-row halves (Cs reuses stage smem) ----
    float* Cs = (float*)smraw;             // 64 x 132 fp32 = 33792 B
    const int which = n0 >> 11;            // 0=q, 1=k, 2=v
    const int h = (n0 & 2047) >> 7;
    const int b = m0 >> 11;
    const int s_base = m0 & 2047;

    #pragma unroll
    for (int half = 0; half < 2; half++) {
        if (wm == half) {
            #pragma unroll
            for (int mf = 0; mf < 4; mf++)
                #pragma unroll
                for (int nf = 0; nf < 8; nf++) {
                    int r0 = mf * 16 + g;
                    int cc = wn * 64 + nf * 8 + q * 2;
                    float2 c01 = { s_[mf][nf][0], s_[mf][nf][1] };
                    float2 c23 = { s_[mf][nf][2], s_[mf][nf][3] };
                    *(float2*)(Cs + (size_t)r0 * LDC + cc) = c01;
                    *(float2*)(Cs + (size_t)(r0 + 8) * LDC + cc) = c23;
                }
        }
        __syncthreads();

        if (which < 2) {
            __half* dstb = (which == 0 ? g_qh : g_kh) + ((size_t)(b * HH + h) * SS) * DD;
            const float scale = (which == 0) ? 0.08838834764831845f : 1.0f;
            #pragma unroll
            for (int i = 0; i < 16; i++) {
                int idx = tid + i * 128;       // 2048 float4 slots
                int row = idx >> 5;            // 0..63
                int c4 = (idx & 31) << 2;
                int s = s_base + half * 64 + row;
                float4 u = *(const float4*)(Cs + row * LDC + c4);
                float4 w = *(const float4*)(Cs + row * LDC + (c4 ^ 64));
                float4 bu = *(const float4*)(bias + n0 + c4);
                float4 bw = *(const float4*)(bias + n0 + (c4 ^ 64));
                u.x += bu.x; u.y += bu.y; u.z += bu.z; u.w += bu.w;
                w.x += bw.x; w.y += bw.y; w.z += bw.z; w.w += bw.w;
                float sgn = (c4 < 64) ? -1.0f : 1.0f;
                const float2* scp = g_sc + (size_t)s * DD + c4;
                float2 sc0 = scp[0], sc1 = scp[1], sc2 = scp[2], sc3 = scp[3];
                float r0 = (u.x * sc0.y + sgn * w.x * sc0.x) * scale;
                float r1 = (u.y * sc1.y + sgn * w.y * sc1.x) * scale;
                float r2 = (u.z * sc2.y + sgn * w.z * sc2.x) * scale;
                float r3 = (u.w * sc3.y + sgn * w.w * sc3.x) * scale;
                __half* dp = dstb + (size_t)s * DD + c4;
                *(__half2*)(dp) = __floats2half2_rn(r0, r1);
                *(__half2*)(dp + 2) = __floats2half2_rn(r2, r3);
            }
        } else {
            __half* dstb = g_vt + ((size_t)(b * HH + h) * DD) * SS + s_base + half * 64;
            #pragma unroll
            for (int i = 0; i < 16; i++) {
                int idx = tid + i * 128;
                int d = idx >> 4;              // 0..127
                int s4 = (idx & 15) << 2;      // 0..60
                float bv = bias[n0 + d];
                float v0 = Cs[(s4 + 0) * LDC + d] + bv;
                float v1 = Cs[(s4 + 1) * LDC + d] + bv;
                float v2 = Cs[(s4 + 2) * LDC + d] + bv;
                float v3 = Cs[(s4 + 3) * LDC + d] + bv;
                __half* dp = dstb + (size_t)d * SS + s4;
                *(__half2*)(dp) = __floats2half2_rn(v0, v1);
                *(__half2*)(dp + 2) = __floats2half2_rn(v2, v3);
            }
        }
        __syncthreads();
    }
}

// ---------------------------------------------------------------------------
// Kernel 3: flash attention, FA2 full-row-warp form.
// 256 threads, 8 warps; each warp owns 16 complete query rows (m16 x n128).
// Softmax fully warp-local; P packs directly into mma A-fragments (registers,
// never smem). K/V double-buffered, ONE __syncthreads per tile iteration.
// smem: Q[128][136] + 2x K + 2x V = 174080 B.
// ---------------------------------------------------------------------------
#define LDH 136
#define ATT_SMEM (5 * 128 * LDH * 2)       // 174080 B

__global__ __launch_bounds__(256, 1) void attn_tc(float* __restrict__ out) {
    extern __shared__ char smraw[];
    __half* Qs = (__half*)smraw;                 // [128][136]
    __half* Ks[2] = { Qs + 128 * LDH, Qs + 2 * 128 * LDH };
    __half* Vs[2] = { Qs + 3 * 128 * LDH, Qs + 4 * 128 * LDH };

    const int tid = threadIdx.x;
    const int wid = tid >> 5;          // 0..7, warp owns rows wid*16..+15
    const int lane = tid & 31;
    const int g = lane >> 2;
    const int q = lane & 3;
    const int s0 = blockIdx.x * 128;
    const int h = blockIdx.y;
    const int b = blockIdx.z;

    const int arow = lane & 15;
    const int akadd = (lane >> 4) << 3;
    const int brow = (lane & 7) + ((lane >> 4) << 3);
    const int bkadd = ((lane >> 3) & 1) << 3;

    const __half* qg = g_qh + ((size_t)(b * HH + h) * SS + s0) * DD;
    const __half* kg = g_kh + ((size_t)(b * HH + h) * SS) * DD;
    const __half* vtg = g_vt + ((size_t)(b * HH + h) * DD) * SS;

    // Prologue: Q, K0, V0 (3 cp groups). 2048 chunks of 8 halves each tile.
    #pragma unroll
    for (int i = 0; i < 8; i++) {
        int idx = tid + i * 256;
        int row = idx >> 4;
        int c8 = (idx & 15) << 3;
        cp_async16(Qs + row * LDH + c8, qg + (size_t)row * DD + c8);
    }
    cp_commit();
    #pragma unroll
    for (int i = 0; i < 8; i++) {
        int idx = tid + i * 256;
        int row = idx >> 4;
        int c8 = (idx & 15) << 3;
        cp_async16(Ks[0] + row * LDH + c8, kg + (size_t)row * DD + c8);
    }
    cp_commit();
    #pragma unroll
    for (int i = 0; i < 8; i++) {
        int idx = tid + i * 256;
        int row = idx >> 4;
        int c8 = (idx & 15) << 3;
        cp_async16(Vs[0] + row * LDH + c8, vtg + (size_t)row * SS + c8);
    }
    cp_commit();

    float o[16][4];
    #pragma unroll
    for (int nf = 0; nf < 16; nf++)
        #pragma unroll
        for (int e = 0; e < 4; e++) o[nf][e] = 0.0f;
    float m_run[2] = {-1e30f, -1e30f};
    float l_run[2] = {0.0f, 0.0f};

    const int NT = SS / 128;           // 16
    for (int t = 0; t < NT; t++) {
        cp_wait<0>();
        __syncthreads();               // K_t, V_t visible; all warps done with t-1

        // Prefetch next K/V into the other buffers (overlaps with compute)
        if (t + 1 < NT) {
            const __half* kn = kg + (size_t)(t + 1) * 128 * DD;
            const __half* vn = vtg + (size_t)(t + 1) * 128;
            __half* kd = Ks[(t + 1) & 1];
            __half* vd = Vs[(t + 1) & 1];
            #pragma unroll
            for (int i = 0; i < 8; i++) {
                int idx = tid + i * 256;
                int row = idx >> 4;
                int c8 = (idx & 15) << 3;
                cp_async16(kd + row * LDH + c8, kn + (size_t)row * DD + c8);
            }
            cp_commit();
            #pragma unroll
            for (int i = 0; i < 8; i++) {
                int idx = tid + i * 256;
                int row = idx >> 4;
                int c8 = (idx & 15) << 3;
                cp_async16(vd + row * LDH + c8, vn + (size_t)row * SS + c8);
            }
            cp_commit();
        }

        const __half* K = Ks[t & 1];
        const __half* V = Vs[t & 1];

        // ---- S = Q K^T : warp-local m16 x n128 ----
        float s_[16][4];
        #pragma unroll
        for (int nf = 0; nf < 16; nf++)
            #pragma unroll
            for (int e = 0; e < 4; e++) s_[nf][e] = 0.0f;

        #pragma unroll
        for (int kk = 0; kk < 8; kk++) {
            unsigned a[4];
            ldsm_x4(a, Qs + (wid * 16 + arow) * LDH + kk * 16 + akadd);
            #pragma unroll
            for (int nb = 0; nb < 8; nb++) {
                unsigned b4[4];
                ldsm_x4(b4, K + (nb * 16 + brow) * LDH + kk * 16 + bkadd);
                mma_f16(s_[2 * nb], a, b4);
                mma_f16(s_[2 * nb + 1], a, b4 + 2);
            }
        }

        // ---- warp-local softmax (rows g and g+8) ----
        float lm[2] = {-1e30f, -1e30f};
        #pragma unroll
        for (int nf = 0; nf < 16; nf++) {
            lm[0] = fmaxf(lm[0], fmaxf(s_[nf][0], s_[nf][1]));
            lm[1] = fmaxf(lm[1], fmaxf(s_[nf][2], s_[nf][3]));
        }
        #pragma unroll
        for (int off = 1; off <= 2; off <<= 1) {
            lm[0] = fmaxf(lm[0], __shfl_xor_sync(0xffffffffu, lm[0], off));
            lm[1] = fmaxf(lm[1], __shfl_xor_sync(0xffffffffu, lm[1], off));
        }
        float mnew[2] = { fmaxf(m_run[0], lm[0]), fmaxf(m_run[1], lm[1]) };
        float al[2] = { __expf(m_run[0] - mnew[0]), __expf(m_run[1] - mnew[1]) };
        m_run[0] = mnew[0]; m_run[1] = mnew[1];

        float ls[2] = {0.0f, 0.0f};
        unsigned p_[16][2];            // packed half2 P fragments (A layout)
        #pragma unroll
        for (int nf = 0; nf < 16; nf++) {
            float p0 = __expf(s_[nf][0] - mnew[0]);
            float p1 = __expf(s_[nf][1] - mnew[0]);
            float p2 = __expf(s_[nf][2] - mnew[1]);
            float p3 = __expf(s_[nf][3] - mnew[1]);
            ls[0] += p0 + p1;
            ls[1] += p2 + p3;
            __half2 h01 = __floats2half2_rn(p0, p1);
            __half2 h23 = __floats2half2_rn(p2, p3);
            p_[nf][0] = *(unsigned*)&h01;
            p_[nf][1] = *(unsigned*)&h23;
        }
        #pragma unroll
        for (int off = 1; off <= 2; off <<= 1) {
            ls[0] += __shfl_xor_sync(0xffffffffu, ls[0], off);
            ls[1] += __shfl_xor_sync(0xffffffffu, ls[1], off);
        }
        l_run[0] = l_run[0] * al[0] + ls[0];
        l_run[1] = l_run[1] * al[1] + ls[1];
        #pragma unroll
        for (int nf = 0; nf < 16; nf++) {
            o[nf][0] *= al[0];
            o[nf][1] *= al[0];
            o[nf][2] *= al[1];
            o[nf][3] *= al[1];
        }

        // ---- O += P V : P from registers, V fragments via ldmatrix ----
        #pragma unroll
        for (int kk = 0; kk < 8; kk++) {
            unsigned a[4] = { p_[2 * kk][0], p_[2 * kk][1],
                              p_[2 * kk + 1][0], p_[2 * kk + 1][1] };
            #pragma unroll
            for (int nb = 0; nb < 8; nb++) {
                unsigned b4[4];
                ldsm_x4(b4, V + (nb * 16 + brow) * LDH + kk * 16 + bkadd);
                mma_f16(o[2 * nb], a, b4);
                mma_f16(o[2 * nb + 1], a, b4 + 2);
            }
        }
        // next iteration's barrier separates these reads from prefetch writes
    }

    // ---- epilogue: normalize, write out[b][s][h][d] ----
    float inv[2] = { 1.0f / l_run[0], 1.0f / l_run[1] };
    #pragma unroll
    for (int nf = 0; nf < 16; nf++) {
        int col = nf * 8 + q * 2;
        int row0 = s0 + wid * 16 + g;
        float2 w0 = { o[nf][0] * inv[0], o[nf][1] * inv[0] };
        float2 w1 = { o[nf][2] * inv[1], o[nf][3] * inv[1] };
        *(float2*)(out + ((size_t)(b * SS + row0) * HH + h) * DD + col) = w0;
        *(float2*)(out + ((size_t)(b * SS + row0 + 8) * HH + h) * DD + col) = w1;
    }
}

// ---------------------------------------------------------------------------
extern "C" void kernel_launch(void* const* d_in, const int* in_sizes, int n_in,
                              void* d_out, int out_size) {
    const float* x    = (const float*)d_in[0];
    const float* W    = (const float*)d_in[1];
    const float* bias = (const float*)d_in[2];
    float* out = (float*)d_out;

    cvt_x<<<(int)((size_t)MM * KK / 2048), 256>>>(x);
    dim3 gw(N3 / 32, KK / 32);
    cvt_wt<<<gw, 256>>>(W);
    sc_table<<<SS * DD / 256, 256>>>();

    cudaFuncSetAttribute(qkv_gemm, cudaFuncAttributeMaxDynamicSharedMemorySize, GEMM_SMEM);
    dim3 g1(N3 / 128, MM / 128);
    qkv_gemm<<<g1, 128, GEMM_SMEM>>>(bias);

    cudaFuncSetAttribute(attn_tc, cudaFuncAttributeMaxDynamicSharedMemorySize, ATT_SMEM);
    dim3 g3(SS / 128, HH, BB);
    attn_tc<<<g3, 256, ATT_SMEM>>>(out);
}